// round 5
// baseline (speedup 1.0000x reference)
#include <cuda_runtime.h>
#include <math.h>

#define N_USERS_C 100000
#define N_ITEMS_C 50000
#define N_NODES_C 150000
#define D_C 64
#define NNZ_C 2400000
#define BATCH_C 2048
#define SCAN_T 1024

// Scratch buffers (allocation-free rule: device globals)
__device__ float g_side[N_NODES_C * D_C];
__device__ float g_ego1[N_NODES_C * D_C];
__device__ float g_ego2[N_NODES_C * D_C];
__device__ int   g_cnt[N_NODES_C];
__device__ int   g_wpos[N_NODES_C];
__device__ int4  g_epack[NNZ_C];          // (row, col, val-bits, 0) grouped by row

// ---------------------------------------------------------------------------
// CSR-order build: zero counts -> histogram -> scan -> reorder
// ---------------------------------------------------------------------------
__global__ void zero_cnt_kernel(int* __restrict__ cnt) {
    int i = blockIdx.x * blockDim.x + threadIdx.x;
    if (i < N_NODES_C) cnt[i] = 0;
}

__global__ void hist_kernel(const int* __restrict__ rows, int* __restrict__ cnt) {
    int e = blockIdx.x * blockDim.x + threadIdx.x;
    if (e < NNZ_C) atomicAdd(&cnt[rows[e]], 1);
}

__global__ __launch_bounds__(SCAN_T)
void scan_kernel(const int* __restrict__ cnt, int* __restrict__ wpos) {
    __shared__ int partials[SCAN_T];
    int tid = threadIdx.x;
    const int CH = (N_NODES_C + SCAN_T - 1) / SCAN_T;   // 147
    int begin = tid * CH;
    int end = begin + CH; if (end > N_NODES_C) end = N_NODES_C;
    int s = 0;
#pragma unroll 8
    for (int i = begin; i < end; i++) s += cnt[i];
    partials[tid] = s;
    __syncthreads();
    for (int off = 1; off < SCAN_T; off <<= 1) {
        int add = (tid >= off) ? partials[tid - off] : 0;
        __syncthreads();
        partials[tid] += add;
        __syncthreads();
    }
    int run = partials[tid] - s;
    for (int i = begin; i < end; i++) {
        wpos[i] = run;
        run += cnt[i];
    }
}

__global__ void reorder_kernel(const int* __restrict__ rows,
                               const int* __restrict__ cols,
                               const float* __restrict__ vals,
                               int* __restrict__ wpos,
                               int4* __restrict__ epack) {
    int e = blockIdx.x * blockDim.x + threadIdx.x;
    if (e >= NNZ_C) return;
    int r = rows[e];
    int p = atomicAdd(&wpos[r], 1);
    epack[p] = make_int4(r, cols[e], __float_as_int(vals[e]), 0);
}

// ---------------------------------------------------------------------------
// zero: clear the scatter accumulator
// ---------------------------------------------------------------------------
__global__ void zero_kernel(float4* __restrict__ p, int n4) {
    int i = blockIdx.x * blockDim.x + threadIdx.x;
    if (i < n4) p[i] = make_float4(0.f, 0.f, 0.f, 0.f);
}

// ---------------------------------------------------------------------------
// Segmented SpMM over row-sorted edges.
// 16 dim-lanes per edge (float4 each). Each 16-lane slot walks 32 consecutive
// sorted edges in batches of 8 (8 edge loads + 8 gathers in flight before any
// dependent FMA), accumulating in registers; flushes with a vector RED only on
// row change. NNZ = 9375 * 256 exactly -> no tail handling.
// ---------------------------------------------------------------------------
#define EPS_C 32   // edges per slot
#define EPB_C 256  // edges per block (8 slots * 32)

__device__ __forceinline__ void red_v4(float4* dst, float4 a) {
    asm volatile("red.global.add.v4.f32 [%0], {%1, %2, %3, %4};"
                 :: "l"(dst), "f"(a.x), "f"(a.y), "f"(a.z), "f"(a.w)
                 : "memory");
}

__global__ __launch_bounds__(128)
void seg_spmm_kernel(const int4* __restrict__ epack,
                     const float4* __restrict__ ego,
                     float4* __restrict__ side) {
    int slot = threadIdx.x >> 4;   // 0..7
    int lane = threadIdx.x & 15;   // float4 slice of the 64-dim row
    int e0 = blockIdx.x * EPB_C + slot * EPS_C;

    float4 acc = make_float4(0.f, 0.f, 0.f, 0.f);
    int cur = -1;

#pragma unroll 1
    for (int e = e0; e < e0 + EPS_C; e += 8) {
        int4 ed[8];
        float4 gv[8];
#pragma unroll
        for (int u = 0; u < 8; u++) ed[u] = epack[e + u];              // broadcast LDG.128
#pragma unroll
        for (int u = 0; u < 8; u++) gv[u] = ego[ed[u].y * 16 + lane];  // coalesced gather
#pragma unroll
        for (int u = 0; u < 8; u++) {
            bool newrow = (ed[u].x != cur);
            if (newrow && cur >= 0)
                red_v4(&side[cur * 16 + lane], acc);
            if (newrow) {
                acc = make_float4(0.f, 0.f, 0.f, 0.f);
                cur = ed[u].x;
            }
            float v = __int_as_float(ed[u].z);
            acc.x = fmaf(v, gv[u].x, acc.x);
            acc.y = fmaf(v, gv[u].y, acc.y);
            acc.z = fmaf(v, gv[u].z, acc.z);
            acc.w = fmaf(v, gv[u].w, acc.w);
        }
    }
    if (cur >= 0)
        red_v4(&side[cur * 16 + lane], acc);
}

// ---------------------------------------------------------------------------
// Dense layer (round-1 version, known good):
// out = l2norm(leaky_relu(side@Wg + (ego*side)@Wb + bg + bb))
// One [M x 128] @ [128 x 64] GEMM with K = [side | ego*side].
// ---------------------------------------------------------------------------
#define TM_C 64
#define KDIM_C 128
#define INS_C 132

__global__ __launch_bounds__(256)
void dense_kernel(const float4* __restrict__ side,
                  const float4* __restrict__ ego,
                  const float4* __restrict__ Wg, const float* __restrict__ bg,
                  const float4* __restrict__ Wb, const float* __restrict__ bb,
                  float4* __restrict__ out, int numTiles) {
    extern __shared__ float smem[];
    float* Wc   = smem;                       // [128][64]
    float* In   = smem + KDIM_C * D_C;        // [64][132]
    float* bsum = In + TM_C * INS_C;          // [64]

    int tid = threadIdx.x;

#pragma unroll
    for (int i = 0; i < 8; i++) {
        int f = tid + i * 256;
        int k = f >> 4, c4 = f & 15;
        float4 w = (k < 64) ? Wg[k * 16 + c4] : Wb[(k - 64) * 16 + c4];
        *(float4*)&Wc[f * 4] = w;
    }
    if (tid < 64) bsum[tid] = bg[tid] + bb[tid];
    __syncthreads();

    int rg = tid >> 4;
    int cg = tid & 15;
    float4 bsv = *(float4*)&bsum[cg * 4];

    for (int tile = blockIdx.x; tile < numTiles; tile += gridDim.x) {
        int row0 = tile * TM_C;
        __syncthreads();

#pragma unroll
        for (int i = 0; i < 4; i++) {
            int f = tid + i * 256;
            int r = f >> 4, k4 = f & 15;
            float4 s  = make_float4(0.f, 0.f, 0.f, 0.f);
            float4 pr = make_float4(0.f, 0.f, 0.f, 0.f);
            int grow = row0 + r;
            if (grow < N_NODES_C) {
                s = side[grow * 16 + k4];
                float4 e = ego[grow * 16 + k4];
                pr = make_float4(s.x * e.x, s.y * e.y, s.z * e.z, s.w * e.w);
            }
            *(float4*)&In[r * INS_C + k4 * 4]      = s;
            *(float4*)&In[r * INS_C + 64 + k4 * 4] = pr;
        }
        __syncthreads();

        float acc[4][4];
#pragma unroll
        for (int i = 0; i < 4; i++)
#pragma unroll
            for (int j = 0; j < 4; j++) acc[i][j] = 0.f;

        const float* Inr = &In[(rg * 4) * INS_C];
#pragma unroll 4
        for (int k = 0; k < KDIM_C; k++) {
            float a0 = Inr[k];
            float a1 = Inr[INS_C + k];
            float a2 = Inr[2 * INS_C + k];
            float a3 = Inr[3 * INS_C + k];
            float4 b = *(const float4*)&Wc[k * 64 + cg * 4];
            acc[0][0] += a0 * b.x; acc[0][1] += a0 * b.y; acc[0][2] += a0 * b.z; acc[0][3] += a0 * b.w;
            acc[1][0] += a1 * b.x; acc[1][1] += a1 * b.y; acc[1][2] += a1 * b.z; acc[1][3] += a1 * b.w;
            acc[2][0] += a2 * b.x; acc[2][1] += a2 * b.y; acc[2][2] += a2 * b.z; acc[2][3] += a2 * b.w;
            acc[3][0] += a3 * b.x; acc[3][1] += a3 * b.y; acc[3][2] += a3 * b.z; acc[3][3] += a3 * b.w;
        }

#pragma unroll
        for (int i = 0; i < 4; i++) {
            float v0 = acc[i][0] + bsv.x;
            float v1 = acc[i][1] + bsv.y;
            float v2 = acc[i][2] + bsv.z;
            float v3 = acc[i][3] + bsv.w;
            v0 = (v0 > 0.f) ? v0 : 0.2f * v0;
            v1 = (v1 > 0.f) ? v1 : 0.2f * v1;
            v2 = (v2 > 0.f) ? v2 : 0.2f * v2;
            v3 = (v3 > 0.f) ? v3 : 0.2f * v3;
            float ss = v0 * v0 + v1 * v1 + v2 * v2 + v3 * v3;
#pragma unroll
            for (int o = 8; o > 0; o >>= 1)
                ss += __shfl_xor_sync(0xffffffffu, ss, o);
            float nrm = sqrtf(ss);
            float scl = 1.0f / fmaxf(nrm, 1e-12f);
            int grow = row0 + rg * 4 + i;
            if (grow < N_NODES_C)
                out[grow * 16 + cg] = make_float4(v0 * scl, v1 * scl, v2 * scl, v3 * scl);
        }
    }
}

// ---------------------------------------------------------------------------
// gamma[b] = sum over 3 embeddings of dot(emb[u], emb[N_USERS+item])
// ---------------------------------------------------------------------------
__global__ void gamma_kernel(const float* __restrict__ x,
                             const int* __restrict__ users,
                             const int* __restrict__ items,
                             float* __restrict__ out) {
    int b = blockIdx.x * 8 + (threadIdx.x >> 5);
    if (b >= BATCH_C) return;
    int lane = threadIdx.x & 31;
    int u  = users[b];
    int it = N_USERS_C + items[b];
    long long ub = (long long)u * D_C, ib = (long long)it * D_C;
    float acc = 0.f;
    acc += x[ub + lane]      * x[ib + lane];
    acc += x[ub + 32 + lane] * x[ib + 32 + lane];
    acc += g_ego1[ub + lane]      * g_ego1[ib + lane];
    acc += g_ego1[ub + 32 + lane] * g_ego1[ib + 32 + lane];
    acc += g_ego2[ub + lane]      * g_ego2[ib + lane];
    acc += g_ego2[ub + 32 + lane] * g_ego2[ib + 32 + lane];
#pragma unroll
    for (int o = 16; o > 0; o >>= 1)
        acc += __shfl_xor_sync(0xffffffffu, acc, o);
    if (lane == 0) out[b] = acc;
}

// ---------------------------------------------------------------------------
extern "C" void kernel_launch(void* const* d_in, const int* in_sizes, int n_in,
                              void* d_out, int out_size) {
    const int*   rows = (const int*)d_in[0];
    const int*   cols = (const int*)d_in[1];
    const float* vals = (const float*)d_in[2];
    const float* x    = (const float*)d_in[3];

    const float *Wg0, *bg0, *Wb0, *bb0, *Wg1, *bg1, *Wb1, *bb1;
    const int *users, *items;
    if (in_sizes[4] == BATCH_C) {
        users = (const int*)d_in[4];
        items = (const int*)d_in[5];
        Wg0 = (const float*)d_in[6];  bg0 = (const float*)d_in[7];
        Wb0 = (const float*)d_in[8];  bb0 = (const float*)d_in[9];
        Wg1 = (const float*)d_in[10]; bg1 = (const float*)d_in[11];
        Wb1 = (const float*)d_in[12]; bb1 = (const float*)d_in[13];
    } else {
        Wg0 = (const float*)d_in[4];  bg0 = (const float*)d_in[5];
        Wb0 = (const float*)d_in[6];  bb0 = (const float*)d_in[7];
        Wg1 = (const float*)d_in[8];  bg1 = (const float*)d_in[9];
        Wb1 = (const float*)d_in[10]; bb1 = (const float*)d_in[11];
        users = (const int*)d_in[12];
        items = (const int*)d_in[13];
    }

    float *side, *ego1, *ego2;
    int *cnt, *wpos;
    int4 *epack;
    cudaGetSymbolAddress((void**)&side,  g_side);
    cudaGetSymbolAddress((void**)&ego1,  g_ego1);
    cudaGetSymbolAddress((void**)&ego2,  g_ego2);
    cudaGetSymbolAddress((void**)&cnt,   g_cnt);
    cudaGetSymbolAddress((void**)&wpos,  g_wpos);
    cudaGetSymbolAddress((void**)&epack, g_epack);

    int smemBytes = (KDIM_C * D_C + TM_C * INS_C + 64) * (int)sizeof(float);
    cudaFuncSetAttribute(dense_kernel, cudaFuncAttributeMaxDynamicSharedMemorySize, smemBytes);

    int numTiles   = (N_NODES_C + TM_C - 1) / TM_C;       // 2344
    int nodeBlocks = (N_NODES_C + 255) / 256;             // 586
    int edgeBlocks = (NNZ_C + 255) / 256;                 // 9375
    int z4 = N_NODES_C * 16;
    int zeroBlocks = (z4 + 255) / 256;
    int spmmBlocks = NNZ_C / EPB_C;                       // 9375

    // Build row-sorted edge list (shared by both layers)
    zero_cnt_kernel<<<nodeBlocks, 256>>>(cnt);
    hist_kernel<<<edgeBlocks, 256>>>(rows, cnt);
    scan_kernel<<<1, SCAN_T>>>(cnt, wpos);
    reorder_kernel<<<edgeBlocks, 256>>>(rows, cols, vals, wpos, epack);

    // Layer 1
    zero_kernel<<<zeroBlocks, 256>>>((float4*)side, z4);
    seg_spmm_kernel<<<spmmBlocks, 128>>>(epack, (const float4*)x, (float4*)side);
    dense_kernel<<<592, 256, smemBytes>>>((const float4*)side, (const float4*)x,
                                          (const float4*)Wg0, bg0,
                                          (const float4*)Wb0, bb0,
                                          (float4*)ego1, numTiles);
    // Layer 2
    zero_kernel<<<zeroBlocks, 256>>>((float4*)side, z4);
    seg_spmm_kernel<<<spmmBlocks, 128>>>(epack, (const float4*)ego1, (float4*)side);
    dense_kernel<<<592, 256, smemBytes>>>((const float4*)side, (const float4*)ego1,
                                          (const float4*)Wg1, bg1,
                                          (const float4*)Wb1, bb1,
                                          (float4*)ego2, numTiles);
    // Final BPR scores
    gamma_kernel<<<BATCH_C / 8, 256>>>(x, users, items, (float*)d_out);
}

// round 6
// speedup vs baseline: 1.1355x; 1.1355x over previous
#include <cuda_runtime.h>
#include <math.h>

#define N_USERS_C 100000
#define N_ITEMS_C 50000
#define N_NODES_C 150000
#define D_C 64
#define NNZ_C 2400000
#define BATCH_C 2048
#define SCB 256
#define NBLK_SCAN ((N_NODES_C + SCB - 1) / SCB)   // 586

// Scratch buffers (allocation-free rule: device globals)
__device__ float g_side[N_NODES_C * D_C];
__device__ float g_ego1[N_NODES_C * D_C];
__device__ float g_ego2[N_NODES_C * D_C];
__device__ int   g_cnt[N_NODES_C];
__device__ int   g_wpos[N_NODES_C];
__device__ int   g_bsum[1024];
__device__ int4  g_epack[NNZ_C];          // (row, col, val-bits, 0) grouped by row

// Packed fp32x2 FMA (sm_103a): lo/hi lanes independent fp32 FMAs
__device__ __forceinline__ unsigned long long fma2(unsigned long long a,
                                                   unsigned long long b,
                                                   unsigned long long c) {
    unsigned long long d;
    asm("fma.rn.f32x2 %0, %1, %2, %3;" : "=l"(d) : "l"(a), "l"(b), "l"(c));
    return d;
}
__device__ __forceinline__ float lo32(unsigned long long v) {
    return __uint_as_float((unsigned)(v & 0xffffffffull));
}
__device__ __forceinline__ float hi32(unsigned long long v) {
    return __uint_as_float((unsigned)(v >> 32));
}

// ---------------------------------------------------------------------------
// CSR-order build: zero counts -> histogram -> hierarchical scan -> reorder
// ---------------------------------------------------------------------------
__global__ void zero_cnt_kernel(int* __restrict__ cnt) {
    int i = blockIdx.x * blockDim.x + threadIdx.x;
    if (i < N_NODES_C) cnt[i] = 0;
}

__global__ void hist_kernel(const int* __restrict__ rows, int* __restrict__ cnt) {
    int e = blockIdx.x * blockDim.x + threadIdx.x;
    if (e < NNZ_C) atomicAdd(&cnt[rows[e]], 1);
}

__global__ void blocksum_kernel(const int* __restrict__ cnt, int* __restrict__ bsum) {
    __shared__ int s[SCB];
    int i = blockIdx.x * SCB + threadIdx.x;
    s[threadIdx.x] = (i < N_NODES_C) ? cnt[i] : 0;
    __syncthreads();
#pragma unroll
    for (int o = SCB / 2; o > 0; o >>= 1) {
        if (threadIdx.x < o) s[threadIdx.x] += s[threadIdx.x + o];
        __syncthreads();
    }
    if (threadIdx.x == 0) bsum[blockIdx.x] = s[0];
}

__global__ __launch_bounds__(1024)
void scan_bsum_kernel(int* __restrict__ bsum) {
    __shared__ int s[1024];
    int tid = threadIdx.x;
    int v = (tid < NBLK_SCAN) ? bsum[tid] : 0;
    s[tid] = v;
    __syncthreads();
    for (int o = 1; o < 1024; o <<= 1) {
        int a = (tid >= o) ? s[tid - o] : 0;
        __syncthreads();
        s[tid] += a;
        __syncthreads();
    }
    if (tid < NBLK_SCAN) bsum[tid] = s[tid] - v;   // exclusive
}

__global__ void scan_final_kernel(const int* __restrict__ cnt,
                                  const int* __restrict__ bsum,
                                  int* __restrict__ wpos) {
    __shared__ int s[SCB];
    int i = blockIdx.x * SCB + threadIdx.x;
    int v = (i < N_NODES_C) ? cnt[i] : 0;
    s[threadIdx.x] = v;
    __syncthreads();
    for (int o = 1; o < SCB; o <<= 1) {
        int a = (threadIdx.x >= o) ? s[threadIdx.x - o] : 0;
        __syncthreads();
        s[threadIdx.x] += a;
        __syncthreads();
    }
    if (i < N_NODES_C) wpos[i] = bsum[blockIdx.x] + s[threadIdx.x] - v;
}

__global__ void reorder_kernel(const int* __restrict__ rows,
                               const int* __restrict__ cols,
                               const float* __restrict__ vals,
                               int* __restrict__ wpos,
                               int4* __restrict__ epack) {
    int e = blockIdx.x * blockDim.x + threadIdx.x;
    if (e >= NNZ_C) return;
    int r = rows[e];
    int p = atomicAdd(&wpos[r], 1);
    epack[p] = make_int4(r, cols[e], __float_as_int(vals[e]), 0);
}

// ---------------------------------------------------------------------------
// zero: clear the scatter accumulator
// ---------------------------------------------------------------------------
__global__ void zero_kernel(float4* __restrict__ p, int n4) {
    int i = blockIdx.x * blockDim.x + threadIdx.x;
    if (i < n4) p[i] = make_float4(0.f, 0.f, 0.f, 0.f);
}

// ---------------------------------------------------------------------------
// Segmented SpMM over row-sorted edges (round-4 config: EPS 16, batch 4).
// ---------------------------------------------------------------------------
#define EPS_C 16   // edges per slot
#define EPB_C 256  // edges per block (16 slots * 16)

__device__ __forceinline__ void red_v4(float4* dst, float4 a) {
    asm volatile("red.global.add.v4.f32 [%0], {%1, %2, %3, %4};"
                 :: "l"(dst), "f"(a.x), "f"(a.y), "f"(a.z), "f"(a.w)
                 : "memory");
}

__global__ __launch_bounds__(256)
void seg_spmm_kernel(const int4* __restrict__ epack,
                     const float4* __restrict__ ego,
                     float4* __restrict__ side) {
    int slot = threadIdx.x >> 4;   // 0..15
    int lane = threadIdx.x & 15;   // float4 slice of the 64-dim row
    int e0 = blockIdx.x * EPB_C + slot * EPS_C;

    float4 acc = make_float4(0.f, 0.f, 0.f, 0.f);
    int cur = -1;

#pragma unroll 1
    for (int e = e0; e < e0 + EPS_C; e += 4) {
        int4 ed[4];
        float4 gv[4];
#pragma unroll
        for (int u = 0; u < 4; u++) ed[u] = epack[e + u];              // broadcast LDG.128
#pragma unroll
        for (int u = 0; u < 4; u++) gv[u] = ego[ed[u].y * 16 + lane];  // coalesced gather
#pragma unroll
        for (int u = 0; u < 4; u++) {
            bool newrow = (ed[u].x != cur);
            if (newrow && cur >= 0)
                red_v4(&side[cur * 16 + lane], acc);
            if (newrow) {
                acc = make_float4(0.f, 0.f, 0.f, 0.f);
                cur = ed[u].x;
            }
            float v = __int_as_float(ed[u].z);
            acc.x = fmaf(v, gv[u].x, acc.x);
            acc.y = fmaf(v, gv[u].y, acc.y);
            acc.z = fmaf(v, gv[u].z, acc.z);
            acc.w = fmaf(v, gv[u].w, acc.w);
        }
    }
    if (cur >= 0)
        red_v4(&side[cur * 16 + lane], acc);
}

// ---------------------------------------------------------------------------
// Dense layer via packed FFMA2 (exact fp32 math):
// out = l2norm(leaky_relu(side@Wg + (ego*side)@Wb + bg + bb))
// One [M x 128] @ [128 x 64] GEMM with K = [side | ego*side].
// W stored as (even-k, odd-k) float2 pairs; acc halves = even/odd-k partials.
// ---------------------------------------------------------------------------
#define TM_C 64
#define KDIM_C 128
#define INS_C 132   // even -> 8B-aligned LDS.64 of (k, k+1)

__global__ __launch_bounds__(256)
void dense_kernel(const float4* __restrict__ side,
                  const float4* __restrict__ ego,
                  const float4* __restrict__ Wg, const float* __restrict__ bg,
                  const float4* __restrict__ Wb, const float* __restrict__ bb,
                  float4* __restrict__ out, int numTiles) {
    extern __shared__ float smem[];
    float* Wc2  = smem;                       // [64 kpair][64 col][2]
    float* In   = smem + KDIM_C * D_C;        // [64 row][132]
    float* bsum = In + TM_C * INS_C;          // [64]

    int tid = threadIdx.x;

    // Stage weights k-pair-interleaved: Wc2[kp*128 + c*2 + (k&1)] = W[k][c]
#pragma unroll
    for (int i = 0; i < 8; i++) {
        int f = tid + i * 256;               // float4 index 0..2047
        int k = f >> 4, c4 = f & 15;
        float4 w = (k < 64) ? Wg[k * 16 + c4] : Wb[(k - 64) * 16 + c4];
        int kp = k >> 1, par = k & 1;
        float* dst = &Wc2[kp * 128 + (c4 * 4) * 2 + par];
        dst[0] = w.x; dst[2] = w.y; dst[4] = w.z; dst[6] = w.w;
    }
    if (tid < 64) bsum[tid] = bg[tid] + bb[tid];
    __syncthreads();

    int rg = tid >> 4;   // rows rg*4..+3
    int cg = tid & 15;   // cols cg*4..+3
    float4 bsv = *(float4*)&bsum[cg * 4];

    for (int tile = blockIdx.x; tile < numTiles; tile += gridDim.x) {
        int row0 = tile * TM_C;
        __syncthreads();

#pragma unroll
        for (int i = 0; i < 4; i++) {
            int f = tid + i * 256;
            int r = f >> 4, k4 = f & 15;
            float4 s  = make_float4(0.f, 0.f, 0.f, 0.f);
            float4 pr = make_float4(0.f, 0.f, 0.f, 0.f);
            int grow = row0 + r;
            if (grow < N_NODES_C) {
                s = side[grow * 16 + k4];
                float4 e = ego[grow * 16 + k4];
                pr = make_float4(s.x * e.x, s.y * e.y, s.z * e.z, s.w * e.w);
            }
            *(float4*)&In[r * INS_C + k4 * 4]      = s;
            *(float4*)&In[r * INS_C + 64 + k4 * 4] = pr;
        }
        __syncthreads();

        unsigned long long acc[4][4];
#pragma unroll
        for (int i = 0; i < 4; i++)
#pragma unroll
            for (int j = 0; j < 4; j++) acc[i][j] = 0ull;

        const float* Inr0 = &In[(rg * 4 + 0) * INS_C];
        const float* Inr1 = &In[(rg * 4 + 1) * INS_C];
        const float* Inr2 = &In[(rg * 4 + 2) * INS_C];
        const float* Inr3 = &In[(rg * 4 + 3) * INS_C];
        const unsigned long long* Wp = (const unsigned long long*)Wc2 + cg * 4;

#pragma unroll 4
        for (int kp = 0; kp < KDIM_C / 2; kp++) {
            unsigned long long a0 = *(const unsigned long long*)(Inr0 + 2 * kp);
            unsigned long long a1 = *(const unsigned long long*)(Inr1 + 2 * kp);
            unsigned long long a2 = *(const unsigned long long*)(Inr2 + 2 * kp);
            unsigned long long a3 = *(const unsigned long long*)(Inr3 + 2 * kp);
            ulonglong2 b01 = *(const ulonglong2*)(Wp + kp * 64);
            ulonglong2 b23 = *(const ulonglong2*)(Wp + kp * 64 + 2);
            acc[0][0] = fma2(a0, b01.x, acc[0][0]);
            acc[0][1] = fma2(a0, b01.y, acc[0][1]);
            acc[0][2] = fma2(a0, b23.x, acc[0][2]);
            acc[0][3] = fma2(a0, b23.y, acc[0][3]);
            acc[1][0] = fma2(a1, b01.x, acc[1][0]);
            acc[1][1] = fma2(a1, b01.y, acc[1][1]);
            acc[1][2] = fma2(a1, b23.x, acc[1][2]);
            acc[1][3] = fma2(a1, b23.y, acc[1][3]);
            acc[2][0] = fma2(a2, b01.x, acc[2][0]);
            acc[2][1] = fma2(a2, b01.y, acc[2][1]);
            acc[2][2] = fma2(a2, b23.x, acc[2][2]);
            acc[2][3] = fma2(a2, b23.y, acc[2][3]);
            acc[3][0] = fma2(a3, b01.x, acc[3][0]);
            acc[3][1] = fma2(a3, b01.y, acc[3][1]);
            acc[3][2] = fma2(a3, b23.x, acc[3][2]);
            acc[3][3] = fma2(a3, b23.y, acc[3][3]);
        }

#pragma unroll
        for (int i = 0; i < 4; i++) {
            float v0 = lo32(acc[i][0]) + hi32(acc[i][0]) + bsv.x;
            float v1 = lo32(acc[i][1]) + hi32(acc[i][1]) + bsv.y;
            float v2 = lo32(acc[i][2]) + hi32(acc[i][2]) + bsv.z;
            float v3 = lo32(acc[i][3]) + hi32(acc[i][3]) + bsv.w;
            v0 = (v0 > 0.f) ? v0 : 0.2f * v0;
            v1 = (v1 > 0.f) ? v1 : 0.2f * v1;
            v2 = (v2 > 0.f) ? v2 : 0.2f * v2;
            v3 = (v3 > 0.f) ? v3 : 0.2f * v3;
            float ss = v0 * v0 + v1 * v1 + v2 * v2 + v3 * v3;
#pragma unroll
            for (int o = 8; o > 0; o >>= 1)
                ss += __shfl_xor_sync(0xffffffffu, ss, o);
            float nrm = sqrtf(ss);
            float scl = 1.0f / fmaxf(nrm, 1e-12f);
            int grow = row0 + rg * 4 + i;
            if (grow < N_NODES_C)
                out[grow * 16 + cg] = make_float4(v0 * scl, v1 * scl, v2 * scl, v3 * scl);
        }
    }
}

// ---------------------------------------------------------------------------
// gamma[b] = sum over 3 embeddings of dot(emb[u], emb[N_USERS+item])
// ---------------------------------------------------------------------------
__global__ void gamma_kernel(const float* __restrict__ x,
                             const int* __restrict__ users,
                             const int* __restrict__ items,
                             float* __restrict__ out) {
    int b = blockIdx.x * 8 + (threadIdx.x >> 5);
    if (b >= BATCH_C) return;
    int lane = threadIdx.x & 31;
    int u  = users[b];
    int it = N_USERS_C + items[b];
    long long ub = (long long)u * D_C, ib = (long long)it * D_C;
    float acc = 0.f;
    acc += x[ub + lane]      * x[ib + lane];
    acc += x[ub + 32 + lane] * x[ib + 32 + lane];
    acc += g_ego1[ub + lane]      * g_ego1[ib + lane];
    acc += g_ego1[ub + 32 + lane] * g_ego1[ib + 32 + lane];
    acc += g_ego2[ub + lane]      * g_ego2[ib + lane];
    acc += g_ego2[ub + 32 + lane] * g_ego2[ib + 32 + lane];
#pragma unroll
    for (int o = 16; o > 0; o >>= 1)
        acc += __shfl_xor_sync(0xffffffffu, acc, o);
    if (lane == 0) out[b] = acc;
}

// ---------------------------------------------------------------------------
extern "C" void kernel_launch(void* const* d_in, const int* in_sizes, int n_in,
                              void* d_out, int out_size) {
    const int*   rows = (const int*)d_in[0];
    const int*   cols = (const int*)d_in[1];
    const float* vals = (const float*)d_in[2];
    const float* x    = (const float*)d_in[3];

    const float *Wg0, *bg0, *Wb0, *bb0, *Wg1, *bg1, *Wb1, *bb1;
    const int *users, *items;
    if (in_sizes[4] == BATCH_C) {
        users = (const int*)d_in[4];
        items = (const int*)d_in[5];
        Wg0 = (const float*)d_in[6];  bg0 = (const float*)d_in[7];
        Wb0 = (const float*)d_in[8];  bb0 = (const float*)d_in[9];
        Wg1 = (const float*)d_in[10]; bg1 = (const float*)d_in[11];
        Wb1 = (const float*)d_in[12]; bb1 = (const float*)d_in[13];
    } else {
        Wg0 = (const float*)d_in[4];  bg0 = (const float*)d_in[5];
        Wb0 = (const float*)d_in[6];  bb0 = (const float*)d_in[7];
        Wg1 = (const float*)d_in[8];  bg1 = (const float*)d_in[9];
        Wb1 = (const float*)d_in[10]; bb1 = (const float*)d_in[11];
        users = (const int*)d_in[12];
        items = (const int*)d_in[13];
    }

    float *side, *ego1, *ego2;
    int *cnt, *wpos, *bsum;
    int4 *epack;
    cudaGetSymbolAddress((void**)&side,  g_side);
    cudaGetSymbolAddress((void**)&ego1,  g_ego1);
    cudaGetSymbolAddress((void**)&ego2,  g_ego2);
    cudaGetSymbolAddress((void**)&cnt,   g_cnt);
    cudaGetSymbolAddress((void**)&wpos,  g_wpos);
    cudaGetSymbolAddress((void**)&bsum,  g_bsum);
    cudaGetSymbolAddress((void**)&epack, g_epack);

    int smemBytes = (KDIM_C * D_C + TM_C * INS_C + 64) * (int)sizeof(float);
    cudaFuncSetAttribute(dense_kernel, cudaFuncAttributeMaxDynamicSharedMemorySize, smemBytes);

    int numTiles   = (N_NODES_C + TM_C - 1) / TM_C;       // 2344
    int edgeBlocks = (NNZ_C + 255) / 256;                 // 9375
    int z4 = N_NODES_C * 16;
    int zeroBlocks = (z4 + 255) / 256;
    int spmmBlocks = NNZ_C / EPB_C;                       // 9375

    // Build row-sorted edge list (shared by both layers)
    zero_cnt_kernel<<<NBLK_SCAN, SCB>>>(cnt);
    hist_kernel<<<edgeBlocks, 256>>>(rows, cnt);
    blocksum_kernel<<<NBLK_SCAN, SCB>>>(cnt, bsum);
    scan_bsum_kernel<<<1, 1024>>>(bsum);
    scan_final_kernel<<<NBLK_SCAN, SCB>>>(cnt, bsum, wpos);
    reorder_kernel<<<edgeBlocks, 256>>>(rows, cols, vals, wpos, epack);

    // Layer 1
    zero_kernel<<<zeroBlocks, 256>>>((float4*)side, z4);
    seg_spmm_kernel<<<spmmBlocks, 256>>>(epack, (const float4*)x, (float4*)side);
    dense_kernel<<<592, 256, smemBytes>>>((const float4*)side, (const float4*)x,
                                          (const float4*)Wg0, bg0,
                                          (const float4*)Wb0, bb0,
                                          (float4*)ego1, numTiles);
    // Layer 2
    zero_kernel<<<zeroBlocks, 256>>>((float4*)side, z4);
    seg_spmm_kernel<<<spmmBlocks, 256>>>(epack, (const float4*)ego1, (float4*)side);
    dense_kernel<<<592, 256, smemBytes>>>((const float4*)side, (const float4*)ego1,
                                          (const float4*)Wg1, bg1,
                                          (const float4*)Wb1, bb1,
                                          (float4*)ego2, numTiles);
    // Final BPR scores
    gamma_kernel<<<BATCH_C / 8, 256>>>(x, users, items, (float*)d_out);
}